// round 13
// baseline (speedup 1.0000x reference)
#include <cuda_runtime.h>

// Problem constants (fixed by the reference)
#define N_SAE  128
#define D_DATA 128
#define D_DICT 512
#define BATCH  1024
#define TB     32     // tokens per MMA batch
#define TCAP   48     // max tokens per expert (mean 16; 8-sigma margin)

typedef unsigned long long u64;
typedef unsigned int u32;

// Cross-CTA combine state (MONOTONIC across graph replays; never reset).
__device__ float g_stage[BATCH * D_DATA];
__device__ int   g_arr  [BATCH];
__device__ int   g_ready[BATCH];

// ---------------- helpers ----------------
__device__ __forceinline__ u64 pk(float lo, float hi) {
    u64 r; asm("mov.b64 %0,{%1,%2};" : "=l"(r) : "f"(lo), "f"(hi)); return r;
}
__device__ __forceinline__ void upk(float& lo, float& hi, u64 v) {
    asm("mov.b64 {%0,%1},%2;" : "=f"(lo), "=f"(hi) : "l"(v));
}
__device__ __forceinline__ u64 add2(u64 a, u64 b) {
    u64 d; asm("add.rn.f32x2 %0,%1,%2;" : "=l"(d) : "l"(a), "l"(b)); return d;
}
__device__ __forceinline__ u32 tf32r(float f) {   // unbiased round-to-nearest tf32
    u32 r; asm("cvt.rna.tf32.f32 %0,%1;" : "=r"(r) : "f"(f)); return r;
}
__device__ __forceinline__ void mma_tf32(float& c0, float& c1, float& c2, float& c3,
                                         u32 a0, u32 a1, u32 a2, u32 a3,
                                         u32 b0, u32 b1) {
    asm("mma.sync.aligned.m16n8k8.row.col.f32.tf32.tf32.f32 "
        "{%0,%1,%2,%3},{%4,%5,%6,%7},{%8,%9},{%0,%1,%2,%3};"
        : "+f"(c0), "+f"(c1), "+f"(c2), "+f"(c3)
        : "r"(a0), "r"(a1), "r"(a2), "r"(a3), "r"(b0), "r"(b1));
}
__device__ __forceinline__ u32 smem_u32(const void* p) {
    u32 a;
    asm("{.reg .u64 t; cvta.to.shared.u64 t,%1; cvt.u32.u64 %0,t;}" : "=r"(a) : "l"(p));
    return a;
}
#define CP16(dst, src) \
    asm volatile("cp.async.ca.shared.global [%0],[%1],16;" :: "r"(dst), "l"(src))
#define CP_COMMIT() asm volatile("cp.async.commit_group;" ::: "memory")
#define CP_WAIT2()  asm volatile("cp.async.wait_group 2;" ::: "memory")

// Dynamic smem (floats). Padded rows (520 / 136): LDS bank = (8t+g+c) mod 32
// for every fragment -> conflict-free.
#define ENC_ROW   520
#define ENC_STAGE (8 * ENC_ROW)             // 4160 floats = 16640 B
#define DEC_ROW   136
#define DEC_STAGE (2 * 8 * DEC_ROW)         // 2176 floats = 8704 B
#define XROW 40
#define OFF_WBUF 0                           // ring: 4*ENC_STAGE = 16640 floats
#define OFF_XS   (4 * ENC_STAGE)            // 16640: xs  [128][40]
#define OFF_ACTS (OFF_XS + D_DATA * XROW)   // 21760: acts[512][40]
#define OFF_PART (OFF_ACTS + D_DICT * XROW) // 42240: part u64[2][16][128]
#define SMEM_FLOATS (OFF_PART + 4096 * 2)
#define SMEM_BYTES  (SMEM_FLOATS * 4)       // 201728 B (1 CTA/SM)

// ---------------------------------------------------------------------------
// One CTA per expert, grid = 128, 512 threads (16 warps).
// Weights stream GMEM -> smem via 4-stage cp.async pipeline; MMA fragments
// come from smem (29-cyc LDS) instead of L2/DRAM-latency scalar LDG.
// ---------------------------------------------------------------------------
__global__ void __launch_bounds__(512, 1)
k_compute(const float* __restrict__ x,
          const float* __restrict__ gate,
          const float* __restrict__ Wenc,
          const float* __restrict__ Wdec,
          const float* __restrict__ benc,
          const float* __restrict__ bdec,
          float* __restrict__ out) {
    int s = blockIdx.x;

    extern __shared__ __align__(16) float smf[];
    float* wbuf = smf + OFF_WBUF;
    float* xs   = smf + OFF_XS;
    float* acts = smf + OFF_ACTS;
    u64*   part = (u64*)(smf + OFF_PART);
    u32 wb0 = smem_u32(wbuf);

    __shared__ float gsf[64];
    __shared__ int prtok[64];
    __shared__ int pj[64];
    __shared__ int sarr[TB];
    __shared__ unsigned masks[32];
    __shared__ int pcnt[32];
    __shared__ int ntot;

    int tid  = threadIdx.x;
    int warp = tid >> 5, lane = tid & 31;
    int g = lane >> 2, t = lane & 3;       // mma fragment coords

    const float* WencS = Wenc + (size_t)s * D_DATA * D_DICT;
    const float* WdecS = Wdec + (size_t)s * D_DICT * D_DATA;

    // ---- Routing: column scan of gate[:, s] (proven) ----
    float v0 = __ldg(&gate[(size_t)tid * N_SAE + s]);
    float v1 = __ldg(&gate[(size_t)(tid + 512) * N_SAE + s]);
    unsigned m0 = __ballot_sync(0xffffffffu, v0 != 0.0f);
    unsigned m1 = __ballot_sync(0xffffffffu, v1 != 0.0f);
    if (lane == 0) { masks[warp] = m0; masks[16 + warp] = m1; }
    if (tid < 64) { prtok[tid] = 0; gsf[tid] = 0.0f; pj[tid] = 0; }
    __syncthreads();
    if (warp == 0) {
        int c = __popc(masks[lane]);
        int ex = c;
        #pragma unroll
        for (int o = 1; o < 32; o <<= 1) {
            int tt = __shfl_up_sync(0xffffffffu, ex, o);
            if (lane >= o) ex += tt;
        }
        pcnt[lane] = ex - c;
        if (lane == 31) ntot = ex;
    }
    __syncthreads();
    int n = ntot; if (n > TCAP) n = TCAP;
    if (n == 0) return;

    if (v0 != 0.0f) {
        int r = pcnt[warp] + __popc(m0 & ((1u << lane) - 1));
        if (r < TCAP) { prtok[r] = tid; gsf[r] = v0; }
    }
    if (v1 != 0.0f) {
        int r = pcnt[16 + warp] + __popc(m1 & ((1u << lane) - 1));
        if (r < TCAP) { prtok[r] = tid + 512; gsf[r] = v1; }
    }
    __syncthreads();

    // ---- Slot j per token (pair id): warp row-scans gate[token] ----
    for (int tk = warp; tk < n; tk += 16) {
        int b = prtok[tk];
        float4 gv = ((const float4*)gate)[(size_t)b * (N_SAE / 4) + lane];
        int e0 = lane * 4;
        int c = (gv.x != 0.0f && e0     < s) + (gv.y != 0.0f && e0 + 1 < s)
              + (gv.z != 0.0f && e0 + 2 < s) + (gv.w != 0.0f && e0 + 3 < s);
        #pragma unroll
        for (int o = 16; o > 0; o >>= 1) c += __shfl_xor_sync(0xffffffffu, c, o);
        if (lane == 0) pj[tk] = b * 2 + c;
    }

    // Staging thread roles
    int erow = tid >> 7, ecol4 = tid & 127;                    // encode: 2 f4/thread
    int dhalf = tid >> 8, drow = (tid >> 5) & 7, dcol4 = tid & 31; // decode: 1 f4/thread

    // ================= Batch loop (usually one iteration) =================
    for (int base = 0; base < n; base += TB) {
        int mb = n - base; if (mb > TB) mb = TB;

        // ---- Encode prologue: prefetch weight stages 0..2 ----
        #pragma unroll
        for (int p = 0; p < 3; p++) {
            const float* src = WencS + (8 * p + erow) * D_DICT + ecol4 * 4;
            u32 dst = wb0 + (p * ENC_STAGE + erow * ENC_ROW + ecol4 * 4) * 4;
            CP16(dst, src);
            CP16(dst + 4 * ENC_ROW * 4, src + 4 * D_DICT);
            CP_COMMIT();
        }

        // ---- xs[d][slot], tf32-rounded (overlaps prefetch) ----
        for (int i = tid; i < D_DATA * TB; i += 512) {
            int j = i & 31, d = i >> 5;
            float v = (j < mb) ? x[(size_t)prtok[base + j] * D_DATA + d] : 0.0f;
            xs[d * XROW + j] = __uint_as_float(tf32r(v));
        }

        // ---------------- Encode: C[512e x 32tok] ----------------
        {
            int e0 = warp * 32;
            float c[2][4][4];
            #pragma unroll
            for (int tau = 0; tau < 2; tau++)
                #pragma unroll
                for (int nt = 0; nt < 4; nt++)
                    #pragma unroll
                    for (int q = 0; q < 4; q++) c[tau][nt][q] = 0.0f;

            #pragma unroll 4
            for (int ks = 0; ks < 16; ks++) {
                CP_WAIT2();
                __syncthreads();          // stage ks ready; slot (ks-1)&3 free
                if (ks + 3 < 16) {
                    int p = ks + 3;
                    const float* src = WencS + (8 * p + erow) * D_DICT + ecol4 * 4;
                    u32 dst = wb0 + ((p & 3) * ENC_STAGE + erow * ENC_ROW + ecol4 * 4) * 4;
                    CP16(dst, src);
                    CP16(dst + 4 * ENC_ROW * 4, src + 4 * D_DICT);
                }
                CP_COMMIT();

                const float* bw = wbuf + (ks & 3) * ENC_STAGE;
                u32 a00 = tf32r(bw[(t    ) * ENC_ROW + e0 + g     ]);
                u32 a01 = tf32r(bw[(t    ) * ENC_ROW + e0 + g +  8]);
                u32 a02 = tf32r(bw[(t + 4) * ENC_ROW + e0 + g     ]);
                u32 a03 = tf32r(bw[(t + 4) * ENC_ROW + e0 + g +  8]);
                u32 a10 = tf32r(bw[(t    ) * ENC_ROW + e0 + g + 16]);
                u32 a11 = tf32r(bw[(t    ) * ENC_ROW + e0 + g + 24]);
                u32 a12 = tf32r(bw[(t + 4) * ENC_ROW + e0 + g + 16]);
                u32 a13 = tf32r(bw[(t + 4) * ENC_ROW + e0 + g + 24]);
                #pragma unroll
                for (int nt = 0; nt < 4; nt++) {
                    u32 b0 = __float_as_uint(xs[(8 * ks + t    ) * XROW + nt * 8 + g]);
                    u32 b1 = __float_as_uint(xs[(8 * ks + t + 4) * XROW + nt * 8 + g]);
                    mma_tf32(c[0][nt][0], c[0][nt][1], c[0][nt][2], c[0][nt][3],
                             a00, a01, a02, a03, b0, b1);
                    mma_tf32(c[1][nt][0], c[1][nt][1], c[1][nt][2], c[1][nt][3],
                             a10, a11, a12, a13, b0, b1);
                }
            }

            // bias + relu + gate + tf32-round -> acts[e][slot]
            #pragma unroll
            for (int tau = 0; tau < 2; tau++) {
                int e = e0 + 16 * tau + g;
                float bg  = benc[(size_t)s * D_DICT + e];
                float bg8 = benc[(size_t)s * D_DICT + e + 8];
                #pragma unroll
                for (int nt = 0; nt < 4; nt++) {
                    int sl = nt * 8 + 2 * t;
                    float gt0 = gsf[base + sl], gt1 = gsf[base + sl + 1];
                    acts[(e    ) * XROW + sl    ] = __uint_as_float(tf32r(fmaxf(c[tau][nt][0] + bg , 0.f) * gt0));
                    acts[(e    ) * XROW + sl + 1] = __uint_as_float(tf32r(fmaxf(c[tau][nt][1] + bg , 0.f) * gt1));
                    acts[(e + 8) * XROW + sl    ] = __uint_as_float(tf32r(fmaxf(c[tau][nt][2] + bg8, 0.f) * gt0));
                    acts[(e + 8) * XROW + sl + 1] = __uint_as_float(tf32r(fmaxf(c[tau][nt][3] + bg8, 0.f) * gt1));
                }
            }
        }

        // ---- Decode prologue: prefetch stages 0..2 (slots 0..2 are free:
        // last encode read was slot 3, and all warps are past iter 12) ----
        #pragma unroll
        for (int p = 0; p < 3; p++) {
            const float* src = WdecS + (dhalf * 256 + 8 * p + drow) * D_DATA + dcol4 * 4;
            u32 dst = wb0 + (p * DEC_STAGE + (dhalf * 8 + drow) * DEC_ROW + dcol4 * 4) * 4;
            CP16(dst, src);
            CP_COMMIT();
        }
        __syncthreads();   // acts visible to all warps

        // ---------------- Decode: C[128d x 32tok] ----------------
        {
            int d0   = (warp & 7) * 16;
            int half = warp >> 3;
            float c[4][4];
            #pragma unroll
            for (int nt = 0; nt < 4; nt++)
                #pragma unroll
                for (int q = 0; q < 4; q++) c[nt][q] = 0.0f;

            #pragma unroll 4
            for (int ks = 0; ks < 32; ks++) {
                CP_WAIT2();
                __syncthreads();
                if (ks + 3 < 32) {
                    int p = ks + 3;
                    const float* src = WdecS + (dhalf * 256 + 8 * p + drow) * D_DATA + dcol4 * 4;
                    u32 dst = wb0 + ((p & 3) * DEC_STAGE + (dhalf * 8 + drow) * DEC_ROW + dcol4 * 4) * 4;
                    CP16(dst, src);
                }
                CP_COMMIT();

                const float* bw = wbuf + (ks & 3) * DEC_STAGE + half * 8 * DEC_ROW;
                u32 a0 = tf32r(bw[(t    ) * DEC_ROW + d0 + g    ]);
                u32 a1 = tf32r(bw[(t    ) * DEC_ROW + d0 + g + 8]);
                u32 a2 = tf32r(bw[(t + 4) * DEC_ROW + d0 + g    ]);
                u32 a3 = tf32r(bw[(t + 4) * DEC_ROW + d0 + g + 8]);
                #pragma unroll
                for (int nt = 0; nt < 4; nt++) {
                    u32 b0 = __float_as_uint(acts[(half * 256 + 8 * ks + t    ) * XROW + nt * 8 + g]);
                    u32 b1 = __float_as_uint(acts[(half * 256 + 8 * ks + t + 4) * XROW + nt * 8 + g]);
                    mma_tf32(c[nt][0], c[nt][1], c[nt][2], c[nt][3],
                             a0, a1, a2, a3, b0, b1);
                }
            }
            #pragma unroll
            for (int nt = 0; nt < 4; nt++) {
                part[half * 2048 + (nt * 4 + t) * 128 + d0 + g    ] = pk(c[nt][0], c[nt][1]);
                part[half * 2048 + (nt * 4 + t) * 128 + d0 + g + 8] = pk(c[nt][2], c[nt][3]);
            }
        }
        __syncthreads();

        // ---- Epilogue: reduce K-halves + b_dec, lock-free combine (proven) ----
        {
            int d  = tid & 127;
            int tl = tid >> 7;             // 0..3; token pairs tl+4q
            float bd = bdec[(size_t)s * D_DATA + d];
            float vv[8];
            #pragma unroll
            for (int q = 0; q < 4; q++) {
                int tp = tl + 4 * q;
                u64 sum = add2(part[tp * 128 + d], part[2048 + tp * 128 + d]);
                float lo, hi; upk(lo, hi, sum);
                vv[2 * q] = lo + bd; vv[2 * q + 1] = hi + bd;
            }

            if (tid < TB) sarr[tid] = (tid < mb) ? atomicAdd(&g_arr[prtok[base + tid]], 1) : 0;
            __syncthreads();

            // Phase 1: publish first-role rows (parity 0).
            #pragma unroll
            for (int q = 0; q < 4; q++) {
                #pragma unroll
                for (int r = 0; r < 2; r++) {
                    int j = 2 * (tl + 4 * q) + r;
                    if (j < mb && (sarr[j] & 1) == 0)
                        __stcg(&g_stage[(size_t)prtok[base + j] * D_DATA + d], vv[2 * q + r]);
                }
            }
            __syncthreads();

            if (tid < mb && (sarr[tid] & 1) == 0) {
                __threadfence();
                atomicAdd(&g_ready[prtok[base + tid]], 1);
            }
            // Phase 2: spin (publish-before-spin => no deadlock).
            if (tid < mb && (sarr[tid] & 1) == 1) {
                int b = prtok[base + tid];
                int want = (sarr[tid] >> 1) + 1;
                while (atomicAdd(&g_ready[b], 0) < want) {}
                __threadfence();
            }
            __syncthreads();

            // Phase 3: combine and write final output (second-role tokens).
            #pragma unroll
            for (int q = 0; q < 4; q++) {
                #pragma unroll
                for (int r = 0; r < 2; r++) {
                    int j = 2 * (tl + 4 * q) + r;
                    if (j < mb && (sarr[j] & 1) == 1) {
                        int b = prtok[base + j];
                        float other = __ldcg(&g_stage[(size_t)b * D_DATA + d]);
                        out[(size_t)b * D_DATA + d] = vv[2 * q + r] + other;
                    }
                }
            }
        }
        __syncthreads();   // before next batch reuses wbuf/xs/acts/part
    }
}

// ---------------------------------------------------------------------------
// Launch. Inputs (metadata order): x, gate, W_enc, W_dec, b_enc, b_dec, k
// ---------------------------------------------------------------------------
extern "C" void kernel_launch(void* const* d_in, const int* in_sizes, int n_in,
                              void* d_out, int out_size) {
    const float* x    = (const float*)d_in[0];
    const float* gate = (const float*)d_in[1];
    const float* Wenc = (const float*)d_in[2];
    const float* Wdec = (const float*)d_in[3];
    const float* benc = (const float*)d_in[4];
    const float* bdec = (const float*)d_in[5];
    float* out = (float*)d_out;

    cudaFuncSetAttribute(k_compute, cudaFuncAttributeMaxDynamicSharedMemorySize,
                         SMEM_BYTES);

    k_compute<<<N_SAE, 512, SMEM_BYTES>>>(x, gate, Wenc, Wdec, benc, bdec, out);
}